// round 2
// baseline (speedup 1.0000x reference)
#include <cuda_runtime.h>
#include <cstdint>

#define BB   16
#define NPTS 4096
#define MPTS 1024
#define C1V  256
#define C2V  256
#define CIN  512
#define H1V  256
#define H2V  256

// Scratch (device globals; allocation-free per harness rules)
__device__ float g_X [(size_t)BB * CIN * NPTS];   // concat(interp, feat1): [B,512,N]  (128 MB)
__device__ float g_X1[(size_t)BB * H1V * NPTS];   // hidden after layer1:   [B,256,N]  (64 MB)
__device__ int   g_idx[(size_t)BB * NPTS * 3];
__device__ float g_w  [(size_t)BB * NPTS * 3];

#define FLT_BIG 3.402823466e38f

// ---------------------------------------------------------------------------
// Kernel 1: 3-NN search. One warp per query point, 8 warps per block.
// xyz2 of the block's batch staged in shared (SoA) with precomputed norms.
// ---------------------------------------------------------------------------
__global__ __launch_bounds__(256) void nn_kernel(const float* __restrict__ xyz1,
                                                 const float* __restrict__ xyz2)
{
    __shared__ float sx[MPTS], sy[MPTS], sz[MPTS], sn[MPTS];
    const int warp = threadIdx.x >> 5;
    const int lane = threadIdx.x & 31;
    const int p0   = blockIdx.x * 8;          // 8 points per block, same batch
    const int b    = p0 / NPTS;               // 512 blocks per batch

    const float* x2 = xyz2 + (size_t)b * MPTS * 3;
    for (int i = threadIdx.x; i < MPTS; i += 256) {
        float a = x2[i*3+0], c = x2[i*3+1], d = x2[i*3+2];
        sx[i] = a; sy[i] = c; sz[i] = d;
        sn[i] = a*a + c*c + d*d;
    }
    __syncthreads();

    const int n = (p0 + warp) % NPTS;
    const float* q = xyz1 + ((size_t)b * NPTS + n) * 3;
    const float qx = q[0], qy = q[1], qz = q[2];
    const float qn = qx*qx + qy*qy + qz*qz;

    float d0 = FLT_BIG, d1 = FLT_BIG, d2 = FLT_BIG;
    int   i0 = -1, i1 = -1, i2 = -1;

    #pragma unroll 4
    for (int j = 0; j < MPTS / 32; j++) {
        const int m = j * 32 + lane;
        const float dot = qx*sx[m] + qy*sy[m] + qz*sz[m];
        const float d = qn + sn[m] - 2.0f * dot;   // matches reference expansion
        if (d < d2) {
            if (d < d1) {
                d2 = d1; i2 = i1;
                if (d < d0) { d1 = d0; i1 = i0; d0 = d; i0 = m; }
                else        { d1 = d;  i1 = m; }
            } else { d2 = d; i2 = m; }
        }
    }

    // 3-round warp arg-min pop merge
    float rd[3]; int ri[3];
    #pragma unroll
    for (int k = 0; k < 3; k++) {
        float v = d0;
        #pragma unroll
        for (int off = 16; off; off >>= 1)
            v = fminf(v, __shfl_xor_sync(0xffffffffu, v, off));
        const unsigned mask = __ballot_sync(0xffffffffu, d0 == v);
        const int src = __ffs(mask) - 1;
        const int widx = __shfl_sync(0xffffffffu, i0, src);
        rd[k] = v; ri[k] = widx;
        if (lane == src) { d0 = d1; i0 = i1; d1 = d2; i1 = i2; d2 = FLT_BIG; i2 = -1; }
    }

    if (lane == 0) {
        const float w0 = 1.0f / (rd[0] + 1e-8f);
        const float w1 = 1.0f / (rd[1] + 1e-8f);
        const float w2 = 1.0f / (rd[2] + 1e-8f);
        const float s  = 1.0f / (w0 + w1 + w2);
        const size_t base = ((size_t)b * NPTS + n) * 3;
        g_w[base+0] = w0 * s; g_w[base+1] = w1 * s; g_w[base+2] = w2 * s;
        g_idx[base+0] = ri[0]; g_idx[base+1] = ri[1]; g_idx[base+2] = ri[2];
    }
}

// ---------------------------------------------------------------------------
// Kernel 2a: interpolation. One block per (b,c) row x n-chunk of 1024.
// feat2 row (4KB) staged in shared; gather by idx, weighted sum, write X.
// ---------------------------------------------------------------------------
__global__ __launch_bounds__(256) void interp_kernel(const float* __restrict__ feat2)
{
    __shared__ float sf[MPTS];
    const int row = blockIdx.x;              // b*C2 + c, 0..4095
    const int b = row / C2V, c = row % C2V;
    const float* f = feat2 + (size_t)row * MPTS;
    for (int i = threadIdx.x; i < MPTS; i += 256) sf[i] = f[i];
    __syncthreads();

    #pragma unroll
    for (int t = 0; t < 4; t++) {
        const int n = blockIdx.y * 1024 + t * 256 + threadIdx.x;
        const size_t base = ((size_t)b * NPTS + n) * 3;
        const int   j0 = g_idx[base+0], j1 = g_idx[base+1], j2 = g_idx[base+2];
        const float w0 = g_w[base+0],   w1 = g_w[base+1],   w2 = g_w[base+2];
        g_X[((size_t)b * CIN + c) * NPTS + n] = w0*sf[j0] + w1*sf[j1] + w2*sf[j2];
    }
}

// ---------------------------------------------------------------------------
// Kernel 2b: copy feat1 into the lower half of X (channels 256..511).
// ---------------------------------------------------------------------------
__global__ __launch_bounds__(256) void copy_feat1_kernel(const float* __restrict__ feat1)
{
    const size_t i4 = (size_t)blockIdx.x * blockDim.x + threadIdx.x;   // float4 index
    const size_t per_b = (size_t)C1V * NPTS / 4;
    const size_t total = (size_t)BB * per_b;
    if (i4 >= total) return;
    const size_t b = i4 / per_b, r = i4 % per_b;
    reinterpret_cast<float4*>(g_X)[b * ((size_t)CIN * NPTS / 4) + (size_t)C2V * NPTS / 4 + r] =
        reinterpret_cast<const float4*>(feat1)[i4];
}

// ---------------------------------------------------------------------------
// Kernel 3: batched SGEMM + BN(eval) + ReLU.
//   C[b][o][n] = relu( scale[o] * sum_k A[o][k]*Bm[b][k][n] + beta[o] )
// 128x128 tile, k-tile 16, 256 threads, 8x8 per thread (split 4+4 halves).
// ---------------------------------------------------------------------------
__global__ __launch_bounds__(256) void gemm_bn_relu_kernel(
    const float* __restrict__ A, const float* __restrict__ Bm,
    const float* __restrict__ gamma, const float* __restrict__ beta,
    float* __restrict__ Cm, int O, int K, int N)
{
    __shared__ __align__(16) float As[16][132];   // [k][o], +4 pad keeps 16B alignment
    __shared__ __align__(16) float Bs[16][128];   // [k][n]

    const int batch = blockIdx.z;
    const float* Bb = Bm + (size_t)batch * K * N;
    float*       Cb = Cm + (size_t)batch * O * N;
    const int o0 = blockIdx.y * 128;
    const int n0 = blockIdx.x * 128;
    const int tid = threadIdx.x;
    const int tx = tid & 15, ty = tid >> 4;

    float acc[8][8];
    #pragma unroll
    for (int r = 0; r < 8; r++)
        #pragma unroll
        for (int c = 0; c < 8; c++) acc[r][c] = 0.0f;

    for (int k0 = 0; k0 < K; k0 += 16) {
        #pragma unroll
        for (int i = 0; i < 8; i++) {            // A tile: 128(o) x 16(k)
            const int idx = tid + i * 256;
            const int ol = idx >> 4, kl = idx & 15;
            As[kl][ol] = A[(size_t)(o0 + ol) * K + k0 + kl];
        }
        #pragma unroll
        for (int i = 0; i < 8; i++) {            // B tile: 16(k) x 128(n), coalesced
            const int idx = tid + i * 256;
            const int kl = idx >> 7, nl = idx & 127;
            Bs[kl][nl] = Bb[(size_t)(k0 + kl) * N + n0 + nl];
        }
        __syncthreads();

        #pragma unroll
        for (int kk = 0; kk < 16; kk++) {
            float4 a0 = *reinterpret_cast<const float4*>(&As[kk][ty * 4]);
            float4 a1 = *reinterpret_cast<const float4*>(&As[kk][64 + ty * 4]);
            float4 b0 = *reinterpret_cast<const float4*>(&Bs[kk][tx * 4]);
            float4 b1 = *reinterpret_cast<const float4*>(&Bs[kk][64 + tx * 4]);
            const float a[8] = {a0.x,a0.y,a0.z,a0.w, a1.x,a1.y,a1.z,a1.w};
            const float bf[8] = {b0.x,b0.y,b0.z,b0.w, b1.x,b1.y,b1.z,b1.w};
            #pragma unroll
            for (int r = 0; r < 8; r++)
                #pragma unroll
                for (int c = 0; c < 8; c++)
                    acc[r][c] = fmaf(a[r], bf[c], acc[r][c]);
        }
        __syncthreads();
    }

    const float inv = rsqrtf(1.0f + 1e-5f);
    #pragma unroll
    for (int r = 0; r < 8; r++) {
        const int o = o0 + ((r < 4) ? (ty * 4 + r) : (64 + ty * 4 + r - 4));
        const float sc = gamma[o] * inv, bi = beta[o];
        #pragma unroll
        for (int c = 0; c < 8; c++) {
            const int n = n0 + ((c < 4) ? (tx * 4 + c) : (64 + tx * 4 + c - 4));
            const float v = fmaf(acc[r][c], sc, bi);
            Cb[(size_t)o * N + n] = v > 0.0f ? v : 0.0f;
        }
    }
}

// ---------------------------------------------------------------------------
extern "C" void kernel_launch(void* const* d_in, const int* in_sizes, int n_in,
                              void* d_out, int out_size)
{
    const float* xyz1   = (const float*)d_in[0];
    const float* xyz2   = (const float*)d_in[1];
    const float* feat1  = (const float*)d_in[2];
    const float* feat2  = (const float*)d_in[3];
    const float* w1     = (const float*)d_in[4];
    const float* gamma1 = (const float*)d_in[5];
    const float* beta1  = (const float*)d_in[6];
    const float* w2     = (const float*)d_in[7];
    const float* gamma2 = (const float*)d_in[8];
    const float* beta2  = (const float*)d_in[9];
    float* out = (float*)d_out;

    float* X;  cudaGetSymbolAddress((void**)&X,  g_X);
    float* X1; cudaGetSymbolAddress((void**)&X1, g_X1);

    // 1) 3-NN (one warp per point)
    nn_kernel<<<BB * NPTS / 8, 256>>>(xyz1, xyz2);

    // 2) build X = [interp(feat2); feat1]
    {
        dim3 grid(BB * C2V, NPTS / 1024);
        interp_kernel<<<grid, 256>>>(feat2);
    }
    {
        const size_t total4 = (size_t)BB * C1V * NPTS / 4;
        copy_feat1_kernel<<<(unsigned)((total4 + 255) / 256), 256>>>(feat1);
    }

    // 3) layer 1: [256,512] x [b,512,4096] -> X1, BN+ReLU
    {
        dim3 grid(NPTS / 128, H1V / 128, BB);
        gemm_bn_relu_kernel<<<grid, 256>>>(w1, X, gamma1, beta1, X1, H1V, CIN, NPTS);
    }
    // 4) layer 2: [256,256] x [b,256,4096] -> out, BN+ReLU
    {
        dim3 grid(NPTS / 128, H2V / 128, BB);
        gemm_bn_relu_kernel<<<grid, 256>>>(w2, X1, gamma2, beta2, out, H2V, H1V, NPTS);
    }
}

// round 5
// speedup vs baseline: 2.1433x; 2.1433x over previous
#include <cuda_runtime.h>
#include <cuda_bf16.h>
#include <cstdint>

#define BB   16
#define NPTS 4096
#define MPTS 1024
#define C1V  256
#define C2V  256
#define CIN  512
#define H1V  256
#define H2V  256

// ---------------------------------------------------------------------------
// Device-global scratch (allocation-free per harness rules)
// ---------------------------------------------------------------------------
__device__ __nv_bfloat16 g_Xh [(size_t)BB * NPTS * CIN];   // X hi  [b][n][k]
__device__ __nv_bfloat16 g_Xl [(size_t)BB * NPTS * CIN];   // X lo
__device__ __nv_bfloat16 g_X1h[(size_t)BB * NPTS * H1V];   // layer1 out hi [b][n][k]
__device__ __nv_bfloat16 g_X1l[(size_t)BB * NPTS * H1V];
__device__ float         g_tf2[(size_t)BB * MPTS * C2V];   // feat2 transposed [b][m][c]
__device__ __nv_bfloat16 g_W1h[H1V * CIN], g_W1l[H1V * CIN];
__device__ __nv_bfloat16 g_W2h[H2V * H1V], g_W2l[H2V * H1V];
__device__ int   g_idx[(size_t)BB * NPTS * 3];
__device__ float g_w  [(size_t)BB * NPTS * 3];

#define FLT_BIG 3.402823466e38f

// ---------------------------------------------------------------------------
// PTX helpers (sm_80-era features only — build targets plain sm_100)
// ---------------------------------------------------------------------------
__device__ __forceinline__ uint32_t smem_u32(const void* p) {
    uint32_t a;
    asm("{ .reg .u64 t; cvta.to.shared.u64 t, %1; cvt.u32.u64 %0, t; }" : "=r"(a) : "l"(p));
    return a;
}
__device__ __forceinline__ void cpa16(uint32_t dst, const void* src) {
    asm volatile("cp.async.cg.shared.global [%0], [%1], 16;" :: "r"(dst), "l"(src));
}
__device__ __forceinline__ void ldmx4(uint32_t* r, uint32_t addr) {
    asm volatile("ldmatrix.sync.aligned.m8n8.x4.shared.b16 {%0,%1,%2,%3}, [%4];"
                 : "=r"(r[0]), "=r"(r[1]), "=r"(r[2]), "=r"(r[3]) : "r"(addr));
}
__device__ __forceinline__ void mma16816(float* d, const uint32_t* a,
                                         uint32_t b0, uint32_t b1) {
    asm volatile(
        "mma.sync.aligned.m16n8k16.row.col.f32.bf16.bf16.f32 "
        "{%0,%1,%2,%3}, {%4,%5,%6,%7}, {%8,%9}, {%0,%1,%2,%3};"
        : "+f"(d[0]), "+f"(d[1]), "+f"(d[2]), "+f"(d[3])
        : "r"(a[0]), "r"(a[1]), "r"(a[2]), "r"(a[3]), "r"(b0), "r"(b1));
}
__device__ __forceinline__ void split2(float y, __nv_bfloat16& h, __nv_bfloat16& l) {
    h = __float2bfloat16_rn(y);
    l = __float2bfloat16_rn(y - __bfloat162float(h));
}

// ---------------------------------------------------------------------------
// Kernel 1: 3-NN search (verified passing in Round 2)
// ---------------------------------------------------------------------------
__global__ __launch_bounds__(256) void nn_kernel(const float* __restrict__ xyz1,
                                                 const float* __restrict__ xyz2)
{
    __shared__ float sx[MPTS], sy[MPTS], sz[MPTS], sn[MPTS];
    const int warp = threadIdx.x >> 5;
    const int lane = threadIdx.x & 31;
    const int p0   = blockIdx.x * 8;
    const int b    = p0 / NPTS;

    const float* x2 = xyz2 + (size_t)b * MPTS * 3;
    for (int i = threadIdx.x; i < MPTS; i += 256) {
        float a = x2[i*3+0], c = x2[i*3+1], d = x2[i*3+2];
        sx[i] = a; sy[i] = c; sz[i] = d;
        sn[i] = a*a + c*c + d*d;
    }
    __syncthreads();

    const int n = (p0 + warp) % NPTS;
    const float* q = xyz1 + ((size_t)b * NPTS + n) * 3;
    const float qx = q[0], qy = q[1], qz = q[2];
    const float qn = qx*qx + qy*qy + qz*qz;

    float d0 = FLT_BIG, d1 = FLT_BIG, d2 = FLT_BIG;
    int   i0 = -1, i1 = -1, i2 = -1;

    #pragma unroll 4
    for (int j = 0; j < MPTS / 32; j++) {
        const int m = j * 32 + lane;
        const float dot = qx*sx[m] + qy*sy[m] + qz*sz[m];
        const float d = qn + sn[m] - 2.0f * dot;
        if (d < d2) {
            if (d < d1) {
                d2 = d1; i2 = i1;
                if (d < d0) { d1 = d0; i1 = i0; d0 = d; i0 = m; }
                else        { d1 = d;  i1 = m; }
            } else { d2 = d; i2 = m; }
        }
    }

    float rd[3]; int ri[3];
    #pragma unroll
    for (int k = 0; k < 3; k++) {
        float v = d0;
        #pragma unroll
        for (int off = 16; off; off >>= 1)
            v = fminf(v, __shfl_xor_sync(0xffffffffu, v, off));
        const unsigned mask = __ballot_sync(0xffffffffu, d0 == v);
        const int src = __ffs(mask) - 1;
        const int widx = __shfl_sync(0xffffffffu, i0, src);
        rd[k] = v; ri[k] = widx;
        if (lane == src) { d0 = d1; i0 = i1; d1 = d2; i1 = i2; d2 = FLT_BIG; i2 = -1; }
    }

    if (lane == 0) {
        const float w0 = 1.0f / (rd[0] + 1e-8f);
        const float w1 = 1.0f / (rd[1] + 1e-8f);
        const float w2 = 1.0f / (rd[2] + 1e-8f);
        const float s  = 1.0f / (w0 + w1 + w2);
        const size_t base = ((size_t)b * NPTS + n) * 3;
        g_w[base+0] = w0 * s; g_w[base+1] = w1 * s; g_w[base+2] = w2 * s;
        g_idx[base+0] = ri[0]; g_idx[base+1] = ri[1]; g_idx[base+2] = ri[2];
    }
}

// ---------------------------------------------------------------------------
// Kernel 2: transpose feat2 [B,C2,M] -> g_tf2 [B,M,C2] (fp32)
// ---------------------------------------------------------------------------
__global__ __launch_bounds__(256) void feat2_T(const float* __restrict__ feat2)
{
    __shared__ float s[32][33];
    const int b = blockIdx.z, c0 = blockIdx.y * 32, m0 = blockIdx.x * 32;
    for (int i = threadIdx.x; i < 1024; i += 256) {
        const int cl = i >> 5, ml = i & 31;
        s[ml][cl] = feat2[((size_t)b * C2V + c0 + cl) * MPTS + m0 + ml];
    }
    __syncthreads();
    for (int i = threadIdx.x; i < 1024; i += 256) {
        const int ml = i >> 5, cl = i & 31;
        g_tf2[((size_t)(b * MPTS + m0 + ml)) * C2V + c0 + cl] = s[ml][cl];
    }
}

// ---------------------------------------------------------------------------
// Kernel 3: interpolate -> X[b][n][0..255] (bf16 hi/lo). One warp per point.
// ---------------------------------------------------------------------------
__global__ __launch_bounds__(256) void interp_t()
{
    const int warp = threadIdx.x >> 5;
    const int lane = threadIdx.x & 31;
    const int gn = blockIdx.x * 8 + warp;
    const int b = gn >> 12;
    const size_t base3 = (size_t)gn * 3;
    const int   j0 = g_idx[base3+0], j1 = g_idx[base3+1], j2 = g_idx[base3+2];
    const float w0 = g_w[base3+0],   w1 = g_w[base3+1],   w2 = g_w[base3+2];
    const float* f0 = g_tf2 + ((size_t)(b * MPTS + j0)) * C2V;
    const float* f1 = g_tf2 + ((size_t)(b * MPTS + j1)) * C2V;
    const float* f2 = g_tf2 + ((size_t)(b * MPTS + j2)) * C2V;
    const size_t orow = (size_t)gn * CIN;

    #pragma unroll
    for (int half = 0; half < 2; half++) {
        const int c = half * 128 + lane * 4;
        const float4 a = *reinterpret_cast<const float4*>(f0 + c);
        const float4 d = *reinterpret_cast<const float4*>(f1 + c);
        const float4 e = *reinterpret_cast<const float4*>(f2 + c);
        float y[4] = { w0*a.x + w1*d.x + w2*e.x, w0*a.y + w1*d.y + w2*e.y,
                       w0*a.z + w1*d.z + w2*e.z, w0*a.w + w1*d.w + w2*e.w };
        __nv_bfloat16 h[4], l[4];
        #pragma unroll
        for (int t = 0; t < 4; t++) split2(y[t], h[t], l[t]);
        *reinterpret_cast<uint2*>(g_Xh + orow + c) = *reinterpret_cast<uint2*>(h);
        *reinterpret_cast<uint2*>(g_Xl + orow + c) = *reinterpret_cast<uint2*>(l);
    }
}

// ---------------------------------------------------------------------------
// Kernel 4: feat1 [B,C1,N] -> X[b][n][256+c] (bf16 hi/lo), tiled transpose
// ---------------------------------------------------------------------------
__global__ __launch_bounds__(256) void feat1_to_X(const float* __restrict__ feat1)
{
    __shared__ float s[32][65];
    const int b = blockIdx.z, c0 = blockIdx.y * 64, n0 = blockIdx.x * 32;
    for (int i = threadIdx.x; i < 64 * 32; i += 256) {
        const int cl = i >> 5, nl = i & 31;
        s[nl][cl] = feat1[((size_t)b * C1V + c0 + cl) * NPTS + n0 + nl];
    }
    __syncthreads();
    const int n_l = threadIdx.x >> 3, seg = threadIdx.x & 7;
    const size_t orow = ((size_t)(b * NPTS + n0 + n_l)) * CIN + C2V + c0 + seg * 8;
    __nv_bfloat16 h[8], l[8];
    #pragma unroll
    for (int t = 0; t < 8; t++) split2(s[n_l][seg * 8 + t], h[t], l[t]);
    *reinterpret_cast<uint4*>(g_Xh + orow) = *reinterpret_cast<uint4*>(h);
    *reinterpret_cast<uint4*>(g_Xl + orow) = *reinterpret_cast<uint4*>(l);
}

// ---------------------------------------------------------------------------
// Kernel 5: split weights to bf16 hi/lo
// ---------------------------------------------------------------------------
__global__ __launch_bounds__(256) void wsplit(const float* __restrict__ w,
                                              __nv_bfloat16* __restrict__ h,
                                              __nv_bfloat16* __restrict__ l, int n)
{
    const int i = blockIdx.x * 256 + threadIdx.x;
    if (i < n) split2(w[i], h[i], l[i]);
}

// ---------------------------------------------------------------------------
// Kernel 6: bf16-split GEMM via mma.sync.m16n8k16 + BN + ReLU.
//   D[o][n] = sum_k W[o][k] * X[n][k], 3 MMA terms (hh, hl, lh), fp32 acc.
// CTA tile 128(o) x 128(n), k-chunk 64, double-buffered cp.async.
// 8 warps in 2(o) x 4(n) grid; warp tile 64 x 32.
// smem buffer layout (64KB each, x2): Wh[0,16K) Wl[16K,32K) Xh[32K,48K) Xl[48K,64K)
// Each region: 128 rows x 128B, XOR-swizzled: byte = row*128 + ((s ^ (row&7))<<4)
// ---------------------------------------------------------------------------
#define SMEM_GEMM 131072

template<int KTOT, bool FP32OUT>
__global__ __launch_bounds__(256, 1)
void gemm_mma(const __nv_bfloat16* __restrict__ Wh, const __nv_bfloat16* __restrict__ Wl,
              const __nv_bfloat16* __restrict__ Bh, const __nv_bfloat16* __restrict__ Bl,
              const float* __restrict__ gamma, const float* __restrict__ beta,
              float* __restrict__ outF, __nv_bfloat16* __restrict__ outH,
              __nv_bfloat16* __restrict__ outL)
{
    extern __shared__ __align__(128) char smem[];
    const uint32_t sb = smem_u32(smem);
    const int tid  = threadIdx.x;
    const int wid  = tid >> 5;
    const int ln   = tid & 31;
    const int wrow = wid >> 2;            // 0..1  (o)
    const int wcol = wid & 3;             // 0..3  (n)
    const int n0   = blockIdx.x * 128;
    const int o0   = blockIdx.y * 128;
    const int b    = blockIdx.z;

    float acc[4][4][4];
    #pragma unroll
    for (int mi = 0; mi < 4; mi++)
        #pragma unroll
        for (int ni = 0; ni < 4; ni++)
            #pragma unroll
            for (int e = 0; e < 4; e++) acc[mi][ni][e] = 0.0f;

    constexpr int NC = KTOT / 64;

    // per-lane ldmatrix row bases (row&7 == ln&7 regardless of tile offset)
    const int rA  = wrow * 64 + (ln & 15);
    const int rB  = wcol * 32 + (ln & 15);
    const uint32_t sunit = (uint32_t)(ln >> 4);   // 0/1: k 0-7 vs 8-15 halves
    const uint32_t lswz  = (uint32_t)(ln & 7);

    // chunk loader
    auto load_chunk = [&](int c) {
        const uint32_t ab = sb + (uint32_t)(c & 1) * 65536u;
        const int k0 = c * 64;
        #pragma unroll
        for (int it = 0; it < 4; it++) {
            const int i = tid + it * 256;
            const int row = i >> 3, s = i & 7;
            const uint32_t sw = (uint32_t)row * 128u + (uint32_t)((s ^ (row & 7)) << 4);
            const size_t wsrc = (size_t)(o0 + row) * KTOT + k0 + s * 8;
            cpa16(ab +          sw, Wh + wsrc);
            cpa16(ab + 16384u + sw, Wl + wsrc);
            const size_t xsrc = ((size_t)b * NPTS + n0 + row) * KTOT + k0 + s * 8;
            cpa16(ab + 32768u + sw, Bh + xsrc);
            cpa16(ab + 49152u + sw, Bl + xsrc);
        }
        asm volatile("cp.async.commit_group;");
    };

    load_chunk(0);

    for (int c = 0; c < NC; c++) {
        if (c + 1 < NC) {
            load_chunk(c + 1);
            asm volatile("cp.async.wait_group 1;" ::: "memory");
        } else {
            asm volatile("cp.async.wait_group 0;" ::: "memory");
        }
        __syncthreads();

        const uint32_t ab = sb + (uint32_t)(c & 1) * 65536u;
        #pragma unroll
        for (int ks = 0; ks < 4; ks++) {
            const uint32_t scol = (uint32_t)(ks * 2) + sunit;
            const uint32_t kswz = ((scol ^ lswz) << 4);

            // B frags: 2 x ldmatrix.x4 covers 4 n-tiles (hi), same for lo
            uint32_t bh[2][4], bl[2][4];
            #pragma unroll
            for (int np = 0; np < 2; np++) {
                const uint32_t boff = (uint32_t)(rB + np * 16) * 128u + kswz;
                ldmx4(bh[np], ab + 32768u + boff);
                ldmx4(bl[np], ab + 49152u + boff);
            }
            #pragma unroll
            for (int mi = 0; mi < 4; mi++) {
                const uint32_t aoff = (uint32_t)(rA + mi * 16) * 128u + kswz;
                uint32_t ah[4], al[4];
                ldmx4(ah, ab + aoff);
                ldmx4(al, ab + 16384u + aoff);
                #pragma unroll
                for (int ni = 0; ni < 4; ni++) {
                    const int np = ni >> 1, hf = ni & 1;
                    const uint32_t b0h = bh[np][hf], b1h = bh[np][2 + hf];
                    const uint32_t b0l = bl[np][hf], b1l = bl[np][2 + hf];
                    mma16816(acc[mi][ni], ah, b0h, b1h);
                    mma16816(acc[mi][ni], ah, b0l, b1l);
                    mma16816(acc[mi][ni], al, b0h, b1h);
                }
            }
        }
        __syncthreads();
    }

    // ---------------- epilogue ----------------
    const float inv = rsqrtf(1.0f + 1e-5f);
    const int g = ln >> 2, t = ln & 3;

    if (FP32OUT) {
        #pragma unroll
        for (int mi = 0; mi < 4; mi++) {
            const int o_a = o0 + wrow * 64 + mi * 16 + g;
            const int o_b = o_a + 8;
            const float scA = gamma[o_a] * inv, biA = beta[o_a];
            const float scB = gamma[o_b] * inv, biB = beta[o_b];
            float* rowA = outF + ((size_t)(b * H2V + o_a)) * NPTS + n0;
            float* rowB = outF + ((size_t)(b * H2V + o_b)) * NPTS + n0;
            #pragma unroll
            for (int ni = 0; ni < 4; ni++) {
                const int n = wcol * 32 + ni * 8 + 2 * t;
                float2 va, vb;
                va.x = fmaxf(fmaf(acc[mi][ni][0], scA, biA), 0.0f);
                va.y = fmaxf(fmaf(acc[mi][ni][1], scA, biA), 0.0f);
                vb.x = fmaxf(fmaf(acc[mi][ni][2], scB, biB), 0.0f);
                vb.y = fmaxf(fmaf(acc[mi][ni][3], scB, biB), 0.0f);
                *reinterpret_cast<float2*>(rowA + n) = va;
                *reinterpret_cast<float2*>(rowB + n) = vb;
            }
        }
    } else {
        // stage BN+ReLU'd fp32 tile [o=128][n=128] (stride 129), then
        // transpose-write bf16 hi/lo [n][o] for next layer
        float* S = reinterpret_cast<float*>(smem);
        __syncthreads();
        #pragma unroll
        for (int mi = 0; mi < 4; mi++) {
            const int ol_a = wrow * 64 + mi * 16 + g;
            const int ol_b = ol_a + 8;
            const float scA = gamma[o0 + ol_a] * inv, biA = beta[o0 + ol_a];
            const float scB = gamma[o0 + ol_b] * inv, biB = beta[o0 + ol_b];
            #pragma unroll
            for (int ni = 0; ni < 4; ni++) {
                const int nl = wcol * 32 + ni * 8 + 2 * t;
                S[ol_a * 129 + nl]     = fmaxf(fmaf(acc[mi][ni][0], scA, biA), 0.0f);
                S[ol_a * 129 + nl + 1] = fmaxf(fmaf(acc[mi][ni][1], scA, biA), 0.0f);
                S[ol_b * 129 + nl]     = fmaxf(fmaf(acc[mi][ni][2], scB, biB), 0.0f);
                S[ol_b * 129 + nl + 1] = fmaxf(fmaf(acc[mi][ni][3], scB, biB), 0.0f);
            }
        }
        __syncthreads();
        const int n_l = tid >> 1, oh = (tid & 1) * 64;
        const size_t drow = ((size_t)(b * NPTS + n0 + n_l)) * H1V + o0 + oh;
        #pragma unroll
        for (int gs = 0; gs < 8; gs++) {
            __nv_bfloat16 h[8], l[8];
            #pragma unroll
            for (int t2 = 0; t2 < 8; t2++)
                split2(S[(oh + gs * 8 + t2) * 129 + n_l], h[t2], l[t2]);
            *reinterpret_cast<uint4*>(outH + drow + gs * 8) = *reinterpret_cast<uint4*>(h);
            *reinterpret_cast<uint4*>(outL + drow + gs * 8) = *reinterpret_cast<uint4*>(l);
        }
    }
}

// ---------------------------------------------------------------------------
extern "C" void kernel_launch(void* const* d_in, const int* in_sizes, int n_in,
                              void* d_out, int out_size)
{
    const float* xyz1   = (const float*)d_in[0];
    const float* xyz2   = (const float*)d_in[1];
    const float* feat1  = (const float*)d_in[2];
    const float* feat2  = (const float*)d_in[3];
    const float* w1     = (const float*)d_in[4];
    const float* gamma1 = (const float*)d_in[5];
    const float* beta1  = (const float*)d_in[6];
    const float* w2     = (const float*)d_in[7];
    const float* gamma2 = (const float*)d_in[8];
    const float* beta2  = (const float*)d_in[9];
    float* out = (float*)d_out;

    __nv_bfloat16 *Xh, *Xl, *X1h, *X1l, *W1h, *W1l, *W2h, *W2l;
    cudaGetSymbolAddress((void**)&Xh,  g_Xh);
    cudaGetSymbolAddress((void**)&Xl,  g_Xl);
    cudaGetSymbolAddress((void**)&X1h, g_X1h);
    cudaGetSymbolAddress((void**)&X1l, g_X1l);
    cudaGetSymbolAddress((void**)&W1h, g_W1h);
    cudaGetSymbolAddress((void**)&W1l, g_W1l);
    cudaGetSymbolAddress((void**)&W2h, g_W2h);
    cudaGetSymbolAddress((void**)&W2l, g_W2l);

    cudaFuncSetAttribute(gemm_mma<CIN, false>, cudaFuncAttributeMaxDynamicSharedMemorySize, SMEM_GEMM);
    cudaFuncSetAttribute(gemm_mma<H1V, true>,  cudaFuncAttributeMaxDynamicSharedMemorySize, SMEM_GEMM);

    nn_kernel<<<BB * NPTS / 8, 256>>>(xyz1, xyz2);
    feat2_T<<<dim3(MPTS / 32, C2V / 32, BB), 256>>>(feat2);
    interp_t<<<BB * NPTS / 8, 256>>>();
    feat1_to_X<<<dim3(NPTS / 32, C1V / 64, BB), 256>>>(feat1);
    wsplit<<<(H1V * CIN + 255) / 256, 256>>>(w1, W1h, W1l, H1V * CIN);
    wsplit<<<(H2V * H1V + 255) / 256, 256>>>(w2, W2h, W2l, H2V * H1V);

    // layer 1: W1[256,512] x X[b, n, 512] -> X1 (bf16 hi/lo, [b][n][256])
    gemm_mma<CIN, false><<<dim3(NPTS / 128, H1V / 128, BB), 256, SMEM_GEMM>>>(
        W1h, W1l, Xh, Xl, gamma1, beta1, nullptr, X1h, X1l);
    // layer 2: W2[256,256] x X1[b, n, 256] -> out fp32 [b][256][n]
    gemm_mma<H1V, true><<<dim3(NPTS / 128, H2V / 128, BB), 256, SMEM_GEMM>>>(
        W2h, W2l, X1h, X1l, gamma2, beta2, out, nullptr, nullptr);
}

// round 7
// speedup vs baseline: 2.3382x; 1.0909x over previous
#include <cuda_runtime.h>
#include <cuda_bf16.h>
#include <cstdint>

#define BB   16
#define NPTS 4096
#define MPTS 1024
#define C1V  256
#define C2V  256
#define CIN  512
#define H1V  256
#define H2V  256

// ---------------------------------------------------------------------------
// Device-global scratch (allocation-free per harness rules)
// ---------------------------------------------------------------------------
__device__ __nv_bfloat16 g_Xh [(size_t)BB * NPTS * CIN];   // X hi  [b][n][k]
__device__ __nv_bfloat16 g_Xl [(size_t)BB * NPTS * CIN];   // X lo
__device__ __nv_bfloat16 g_X1h[(size_t)BB * NPTS * H1V];   // layer1 out hi [b][n][k]
__device__ __nv_bfloat16 g_X1l[(size_t)BB * NPTS * H1V];
__device__ float         g_tf2[(size_t)BB * MPTS * C2V];   // feat2 transposed [b][m][c]
__device__ __nv_bfloat16 g_W1h[H1V * CIN], g_W1l[H1V * CIN];
__device__ __nv_bfloat16 g_W2h[H2V * H1V], g_W2l[H2V * H1V];
__device__ int   g_idx[(size_t)BB * NPTS * 3];
__device__ float g_w  [(size_t)BB * NPTS * 3];

#define FLT_BIG 3.402823466e38f

// ---------------------------------------------------------------------------
// PTX helpers (sm_80-era features only — build targets plain sm_100)
// ---------------------------------------------------------------------------
__device__ __forceinline__ uint32_t smem_u32(const void* p) {
    uint32_t a;
    asm("{ .reg .u64 t; cvta.to.shared.u64 t, %1; cvt.u32.u64 %0, t; }" : "=r"(a) : "l"(p));
    return a;
}
__device__ __forceinline__ void cpa16(uint32_t dst, const void* src) {
    asm volatile("cp.async.cg.shared.global [%0], [%1], 16;" :: "r"(dst), "l"(src));
}
__device__ __forceinline__ void ldmx4(uint32_t* r, uint32_t addr) {
    asm volatile("ldmatrix.sync.aligned.m8n8.x4.shared.b16 {%0,%1,%2,%3}, [%4];"
                 : "=r"(r[0]), "=r"(r[1]), "=r"(r[2]), "=r"(r[3]) : "r"(addr));
}
__device__ __forceinline__ void mma16816(float* d, const uint32_t* a,
                                         uint32_t b0, uint32_t b1) {
    asm volatile(
        "mma.sync.aligned.m16n8k16.row.col.f32.bf16.bf16.f32 "
        "{%0,%1,%2,%3}, {%4,%5,%6,%7}, {%8,%9}, {%0,%1,%2,%3};"
        : "+f"(d[0]), "+f"(d[1]), "+f"(d[2]), "+f"(d[3])
        : "r"(a[0]), "r"(a[1]), "r"(a[2]), "r"(a[3]), "r"(b0), "r"(b1));
}
__device__ __forceinline__ void split2(float y, __nv_bfloat16& h, __nv_bfloat16& l) {
    h = __float2bfloat16_rn(y);
    l = __float2bfloat16_rn(y - __bfloat162float(h));
}

// ---------------------------------------------------------------------------
// Fused heterogeneous prep kernel. 256 threads/block.
// Block map (interleaved so ALU-bound nn and DRAM-bound feat1 share waves):
//   [0, 16384): even -> nn part (8192), odd -> feat1_to_X part (8192)
//   [16384, 20480): feat2_T part (4096)
//   [20480, 21248): weight split part (768)
// ---------------------------------------------------------------------------
#define NN_BLKS   (BB * NPTS / 8)                         // 8192
#define F1_BLKS   ((NPTS / 32) * (C1V / 64) * BB)         // 8192
#define F2T_BLKS  ((MPTS / 32) * (C2V / 32) * BB)         // 4096
#define WS1_BLKS  (H1V * CIN / 256)                       // 512
#define WS2_BLKS  (H2V * H1V / 256)                       // 256
#define PREP_BLKS (NN_BLKS + F1_BLKS + F2T_BLKS + WS1_BLKS + WS2_BLKS)

__global__ __launch_bounds__(256) void prep_kernel(
    const float* __restrict__ xyz1, const float* __restrict__ xyz2,
    const float* __restrict__ feat1, const float* __restrict__ feat2,
    const float* __restrict__ w1, const float* __restrict__ w2)
{
    __shared__ __align__(16) char sbuf[16384];
    const int bid = blockIdx.x;
    const int tid = threadIdx.x;

    if (bid < NN_BLKS + F1_BLKS) {
        if ((bid & 1) == 0) {
            // ---------------- nn part ----------------
            float* sx = reinterpret_cast<float*>(sbuf);
            float* sy = sx + MPTS;
            float* sz = sy + MPTS;
            float* sn = sz + MPTS;
            const int warp = tid >> 5;
            const int lane = tid & 31;
            const int p0   = (bid >> 1) * 8;
            const int b    = p0 / NPTS;

            const float* x2 = xyz2 + (size_t)b * MPTS * 3;
            for (int i = tid; i < MPTS; i += 256) {
                float a = x2[i*3+0], c = x2[i*3+1], d = x2[i*3+2];
                sx[i] = a; sy[i] = c; sz[i] = d;
                sn[i] = a*a + c*c + d*d;
            }
            __syncthreads();

            const int n = (p0 + warp) % NPTS;
            const float* q = xyz1 + ((size_t)b * NPTS + n) * 3;
            const float qx = q[0], qy = q[1], qz = q[2];
            const float qn = qx*qx + qy*qy + qz*qz;

            float d0 = FLT_BIG, d1 = FLT_BIG, d2 = FLT_BIG;
            int   i0 = -1, i1 = -1, i2 = -1;

            #pragma unroll 4
            for (int j = 0; j < MPTS / 32; j++) {
                const int m = j * 32 + lane;
                const float dot = qx*sx[m] + qy*sy[m] + qz*sz[m];
                const float d = qn + sn[m] - 2.0f * dot;
                if (d < d2) {
                    if (d < d1) {
                        d2 = d1; i2 = i1;
                        if (d < d0) { d1 = d0; i1 = i0; d0 = d; i0 = m; }
                        else        { d1 = d;  i1 = m; }
                    } else { d2 = d; i2 = m; }
                }
            }

            float rd[3]; int ri[3];
            #pragma unroll
            for (int k = 0; k < 3; k++) {
                float v = d0;
                #pragma unroll
                for (int off = 16; off; off >>= 1)
                    v = fminf(v, __shfl_xor_sync(0xffffffffu, v, off));
                const unsigned mask = __ballot_sync(0xffffffffu, d0 == v);
                const int src = __ffs(mask) - 1;
                const int widx = __shfl_sync(0xffffffffu, i0, src);
                rd[k] = v; ri[k] = widx;
                if (lane == src) { d0 = d1; i0 = i1; d1 = d2; i1 = i2; d2 = FLT_BIG; i2 = -1; }
            }

            if (lane == 0) {
                const float w0 = 1.0f / (rd[0] + 1e-8f);
                const float w1v = 1.0f / (rd[1] + 1e-8f);
                const float w2v = 1.0f / (rd[2] + 1e-8f);
                const float s  = 1.0f / (w0 + w1v + w2v);
                const size_t base = ((size_t)b * NPTS + n) * 3;
                g_w[base+0] = w0 * s; g_w[base+1] = w1v * s; g_w[base+2] = w2v * s;
                g_idx[base+0] = ri[0]; g_idx[base+1] = ri[1]; g_idx[base+2] = ri[2];
            }
        } else {
            // ---------------- feat1 -> X part ----------------
            float (*s)[65] = reinterpret_cast<float(*)[65]>(sbuf);
            const int f  = bid >> 1;
            const int n0 = (f & 127) * 32;          // NPTS/32 = 128
            const int c0 = ((f >> 7) & 3) * 64;     // C1V/64 = 4
            const int b  = f >> 9;
            for (int i = tid; i < 64 * 32; i += 256) {
                const int cl = i >> 5, nl = i & 31;
                s[nl][cl] = feat1[((size_t)b * C1V + c0 + cl) * NPTS + n0 + nl];
            }
            __syncthreads();
            const int n_l = tid >> 3, seg = tid & 7;
            const size_t orow = ((size_t)(b * NPTS + n0 + n_l)) * CIN + C2V + c0 + seg * 8;
            __nv_bfloat16 h[8], l[8];
            #pragma unroll
            for (int t = 0; t < 8; t++) split2(s[n_l][seg * 8 + t], h[t], l[t]);
            *reinterpret_cast<uint4*>(g_Xh + orow) = *reinterpret_cast<uint4*>(h);
            *reinterpret_cast<uint4*>(g_Xl + orow) = *reinterpret_cast<uint4*>(l);
        }
    } else if (bid < NN_BLKS + F1_BLKS + F2T_BLKS) {
        // ---------------- feat2 transpose part ----------------
        float (*s)[33] = reinterpret_cast<float(*)[33]>(sbuf);
        const int t  = bid - (NN_BLKS + F1_BLKS);
        const int m0 = (t & 31) * 32;               // MPTS/32 = 32
        const int c0 = ((t >> 5) & 7) * 32;         // C2V/32 = 8
        const int b  = t >> 8;
        for (int i = tid; i < 1024; i += 256) {
            const int cl = i >> 5, ml = i & 31;
            s[ml][cl] = feat2[((size_t)b * C2V + c0 + cl) * MPTS + m0 + ml];
        }
        __syncthreads();
        for (int i = tid; i < 1024; i += 256) {
            const int ml = i >> 5, cl = i & 31;
            g_tf2[((size_t)(b * MPTS + m0 + ml)) * C2V + c0 + cl] = s[ml][cl];
        }
    } else {
        // ---------------- weight split part ----------------
        const int u = bid - (NN_BLKS + F1_BLKS + F2T_BLKS);
        if (u < WS1_BLKS) {
            const int i = u * 256 + tid;
            split2(w1[i], g_W1h[i], g_W1l[i]);
        } else {
            const int i = (u - WS1_BLKS) * 256 + tid;
            split2(w2[i], g_W2h[i], g_W2l[i]);
        }
    }
}

// ---------------------------------------------------------------------------
// interpolate -> X[b][n][0..255] (bf16 hi/lo). One warp per point.
// ---------------------------------------------------------------------------
__global__ __launch_bounds__(256) void interp_t()
{
    const int warp = threadIdx.x >> 5;
    const int lane = threadIdx.x & 31;
    const int gn = blockIdx.x * 8 + warp;
    const int b = gn >> 12;
    const size_t base3 = (size_t)gn * 3;
    const int   j0 = g_idx[base3+0], j1 = g_idx[base3+1], j2 = g_idx[base3+2];
    const float w0 = g_w[base3+0],   w1 = g_w[base3+1],   w2 = g_w[base3+2];
    const float* f0 = g_tf2 + ((size_t)(b * MPTS + j0)) * C2V;
    const float* f1 = g_tf2 + ((size_t)(b * MPTS + j1)) * C2V;
    const float* f2 = g_tf2 + ((size_t)(b * MPTS + j2)) * C2V;
    const size_t orow = (size_t)gn * CIN;

    #pragma unroll
    for (int half = 0; half < 2; half++) {
        const int c = half * 128 + lane * 4;
        const float4 a = *reinterpret_cast<const float4*>(f0 + c);
        const float4 d = *reinterpret_cast<const float4*>(f1 + c);
        const float4 e = *reinterpret_cast<const float4*>(f2 + c);
        float y[4] = { w0*a.x + w1*d.x + w2*e.x, w0*a.y + w1*d.y + w2*e.y,
                       w0*a.z + w1*d.z + w2*e.z, w0*a.w + w1*d.w + w2*e.w };
        __nv_bfloat16 h[4], l[4];
        #pragma unroll
        for (int t = 0; t < 4; t++) split2(y[t], h[t], l[t]);
        *reinterpret_cast<uint2*>(g_Xh + orow + c) = *reinterpret_cast<uint2*>(h);
        *reinterpret_cast<uint2*>(g_Xl + orow + c) = *reinterpret_cast<uint2*>(l);
    }
}

// ---------------------------------------------------------------------------
// bf16-split GEMM via mma.sync.m16n8k16 + BN + ReLU (unchanged from R5 pass)
// ---------------------------------------------------------------------------
#define SMEM_GEMM 131072

template<int KTOT, bool FP32OUT>
__global__ __launch_bounds__(256, 1)
void gemm_mma(const __nv_bfloat16* __restrict__ Wh, const __nv_bfloat16* __restrict__ Wl,
              const __nv_bfloat16* __restrict__ Bh, const __nv_bfloat16* __restrict__ Bl,
              const float* __restrict__ gamma, const float* __restrict__ beta,
              float* __restrict__ outF, __nv_bfloat16* __restrict__ outH,
              __nv_bfloat16* __restrict__ outL)
{
    extern __shared__ __align__(128) char smem[];
    const uint32_t sb = smem_u32(smem);
    const int tid  = threadIdx.x;
    const int wid  = tid >> 5;
    const int ln   = tid & 31;
    const int wrow = wid >> 2;
    const int wcol = wid & 3;
    const int n0   = blockIdx.x * 128;
    const int o0   = blockIdx.y * 128;
    const int b    = blockIdx.z;

    float acc[4][4][4];
    #pragma unroll
    for (int mi = 0; mi < 4; mi++)
        #pragma unroll
        for (int ni = 0; ni < 4; ni++)
            #pragma unroll
            for (int e = 0; e < 4; e++) acc[mi][ni][e] = 0.0f;

    constexpr int NC = KTOT / 64;

    const int rA  = wrow * 64 + (ln & 15);
    const int rB  = wcol * 32 + (ln & 15);
    const uint32_t sunit = (uint32_t)(ln >> 4);
    const uint32_t lswz  = (uint32_t)(ln & 7);

    auto load_chunk = [&](int c) {
        const uint32_t ab = sb + (uint32_t)(c & 1) * 65536u;
        const int k0 = c * 64;
        #pragma unroll
        for (int it = 0; it < 4; it++) {
            const int i = tid + it * 256;
            const int row = i >> 3, s = i & 7;
            const uint32_t sw = (uint32_t)row * 128u + (uint32_t)((s ^ (row & 7)) << 4);
            const size_t wsrc = (size_t)(o0 + row) * KTOT + k0 + s * 8;
            cpa16(ab +          sw, Wh + wsrc);
            cpa16(ab + 16384u + sw, Wl + wsrc);
            const size_t xsrc = ((size_t)b * NPTS + n0 + row) * KTOT + k0 + s * 8;
            cpa16(ab + 32768u + sw, Bh + xsrc);
            cpa16(ab + 49152u + sw, Bl + xsrc);
        }
        asm volatile("cp.async.commit_group;");
    };

    load_chunk(0);

    for (int c = 0; c < NC; c++) {
        if (c + 1 < NC) {
            load_chunk(c + 1);
            asm volatile("cp.async.wait_group 1;" ::: "memory");
        } else {
            asm volatile("cp.async.wait_group 0;" ::: "memory");
        }
        __syncthreads();

        const uint32_t ab = sb + (uint32_t)(c & 1) * 65536u;
        #pragma unroll
        for (int ks = 0; ks < 4; ks++) {
            const uint32_t scol = (uint32_t)(ks * 2) + sunit;
            const uint32_t kswz = ((scol ^ lswz) << 4);

            uint32_t bh[2][4], bl[2][4];
            #pragma unroll
            for (int np = 0; np < 2; np++) {
                const uint32_t boff = (uint32_t)(rB + np * 16) * 128u + kswz;
                ldmx4(bh[np], ab + 32768u + boff);
                ldmx4(bl[np], ab + 49152u + boff);
            }
            #pragma unroll
            for (int mi = 0; mi < 4; mi++) {
                const uint32_t aoff = (uint32_t)(rA + mi * 16) * 128u + kswz;
                uint32_t ah[4], al[4];
                ldmx4(ah, ab + aoff);
                ldmx4(al, ab + 16384u + aoff);
                #pragma unroll
                for (int ni = 0; ni < 4; ni++) {
                    const int np = ni >> 1, hf = ni & 1;
                    const uint32_t b0h = bh[np][hf], b1h = bh[np][2 + hf];
                    const uint32_t b0l = bl[np][hf], b1l = bl[np][2 + hf];
                    mma16816(acc[mi][ni], ah, b0h, b1h);
                    mma16816(acc[mi][ni], ah, b0l, b1l);
                    mma16816(acc[mi][ni], al, b0h, b1h);
                }
            }
        }
        __syncthreads();
    }

    const float inv = rsqrtf(1.0f + 1e-5f);
    const int g = ln >> 2, t = ln & 3;

    if (FP32OUT) {
        #pragma unroll
        for (int mi = 0; mi < 4; mi++) {
            const int o_a = o0 + wrow * 64 + mi * 16 + g;
            const int o_b = o_a + 8;
            const float scA = gamma[o_a] * inv, biA = beta[o_a];
            const float scB = gamma[o_b] * inv, biB = beta[o_b];
            float* rowA = outF + ((size_t)(b * H2V + o_a)) * NPTS + n0;
            float* rowB = outF + ((size_t)(b * H2V + o_b)) * NPTS + n0;
            #pragma unroll
            for (int ni = 0; ni < 4; ni++) {
                const int n = wcol * 32 + ni * 8 + 2 * t;
                float2 va, vb;
                va.x = fmaxf(fmaf(acc[mi][ni][0], scA, biA), 0.0f);
                va.y = fmaxf(fmaf(acc[mi][ni][1], scA, biA), 0.0f);
                vb.x = fmaxf(fmaf(acc[mi][ni][2], scB, biB), 0.0f);
                vb.y = fmaxf(fmaf(acc[mi][ni][3], scB, biB), 0.0f);
                *reinterpret_cast<float2*>(rowA + n) = va;
                *reinterpret_cast<float2*>(rowB + n) = vb;
            }
        }
    } else {
        float* S = reinterpret_cast<float*>(smem);
        __syncthreads();
        #pragma unroll
        for (int mi = 0; mi < 4; mi++) {
            const int ol_a = wrow * 64 + mi * 16 + g;
            const int ol_b = ol_a + 8;
            const float scA = gamma[o0 + ol_a] * inv, biA = beta[o0 + ol_a];
            const float scB = gamma[o0 + ol_b] * inv, biB = beta[o0 + ol_b];
            #pragma unroll
            for (int ni = 0; ni < 4; ni++) {
                const int nl = wcol * 32 + ni * 8 + 2 * t;
                S[ol_a * 129 + nl]     = fmaxf(fmaf(acc[mi][ni][0], scA, biA), 0.0f);
                S[ol_a * 129 + nl + 1] = fmaxf(fmaf(acc[mi][ni][1], scA, biA), 0.0f);
                S[ol_b * 129 + nl]     = fmaxf(fmaf(acc[mi][ni][2], scB, biB), 0.0f);
                S[ol_b * 129 + nl + 1] = fmaxf(fmaf(acc[mi][ni][3], scB, biB), 0.0f);
            }
        }
        __syncthreads();
        const int n_l = tid >> 1, oh = (tid & 1) * 64;
        const size_t drow = ((size_t)(b * NPTS + n0 + n_l)) * H1V + o0 + oh;
        #pragma unroll
        for (int gs = 0; gs < 8; gs++) {
            __nv_bfloat16 h[8], l[8];
            #pragma unroll
            for (int t2 = 0; t2 < 8; t2++)
                split2(S[(oh + gs * 8 + t2) * 129 + n_l], h[t2], l[t2]);
            *reinterpret_cast<uint4*>(outH + drow + gs * 8) = *reinterpret_cast<uint4*>(h);
            *reinterpret_cast<uint4*>(outL + drow + gs * 8) = *reinterpret_cast<uint4*>(l);
        }
    }
}

// ---------------------------------------------------------------------------
extern "C" void kernel_launch(void* const* d_in, const int* in_sizes, int n_in,
                              void* d_out, int out_size)
{
    const float* xyz1   = (const float*)d_in[0];
    const float* xyz2   = (const float*)d_in[1];
    const float* feat1  = (const float*)d_in[2];
    const float* feat2  = (const float*)d_in[3];
    const float* w1     = (const float*)d_in[4];
    const float* gamma1 = (const float*)d_in[5];
    const float* beta1  = (const float*)d_in[6];
    const float* w2     = (const float*)d_in[7];
    const float* gamma2 = (const float*)d_in[8];
    const float* beta2  = (const float*)d_in[9];
    float* out = (float*)d_out;

    __nv_bfloat16 *Xh, *Xl, *X1h, *X1l, *W1h, *W1l, *W2h, *W2l;
    cudaGetSymbolAddress((void**)&Xh,  g_Xh);
    cudaGetSymbolAddress((void**)&Xl,  g_Xl);
    cudaGetSymbolAddress((void**)&X1h, g_X1h);
    cudaGetSymbolAddress((void**)&X1l, g_X1l);
    cudaGetSymbolAddress((void**)&W1h, g_W1h);
    cudaGetSymbolAddress((void**)&W1l, g_W1l);
    cudaGetSymbolAddress((void**)&W2h, g_W2h);
    cudaGetSymbolAddress((void**)&W2l, g_W2l);

    cudaFuncSetAttribute(gemm_mma<CIN, false>, cudaFuncAttributeMaxDynamicSharedMemorySize, SMEM_GEMM);
    cudaFuncSetAttribute(gemm_mma<H1V, true>,  cudaFuncAttributeMaxDynamicSharedMemorySize, SMEM_GEMM);

    // 1) fused heterogeneous prep (nn + feat1->X + feat2 transpose + wsplit)
    prep_kernel<<<PREP_BLKS, 256>>>(xyz1, xyz2, feat1, feat2, w1, w2);

    // 2) interpolation (depends on nn + feat2_T)
    interp_t<<<BB * NPTS / 8, 256>>>();

    // 3) layer 1: W1[256,512] x X[b, n, 512] -> X1 (bf16 hi/lo, [b][n][256])
    gemm_mma<CIN, false><<<dim3(NPTS / 128, H1V / 128, BB), 256, SMEM_GEMM>>>(
        W1h, W1l, Xh, Xl, gamma1, beta1, nullptr, X1h, X1l);
    // 4) layer 2: W2[256,256] x X1[b, n, 256] -> out fp32 [b][256][n]
    gemm_mma<H1V, true><<<dim3(NPTS / 128, H2V / 128, BB), 256, SMEM_GEMM>>>(
        W2h, W2l, X1h, X1l, gamma2, beta2, out, nullptr, nullptr);
}

// round 8
// speedup vs baseline: 2.3585x; 1.0087x over previous
#include <cuda_runtime.h>
#include <cuda_bf16.h>
#include <cstdint>

#define BB   16
#define NPTS 4096
#define MPTS 1024
#define C1V  256
#define C2V  256
#define CIN  512
#define H1V  256
#define H2V  256

// ---------------------------------------------------------------------------
// Device-global scratch (allocation-free per harness rules)
// ---------------------------------------------------------------------------
__device__ __nv_bfloat16 g_Xh [(size_t)BB * NPTS * CIN];   // X hi  [b][n][k]
__device__ __nv_bfloat16 g_Xl [(size_t)BB * NPTS * CIN];   // X lo
__device__ __nv_bfloat16 g_X1h[(size_t)BB * NPTS * H1V];   // layer1 out hi [b][n][k]
__device__ __nv_bfloat16 g_X1l[(size_t)BB * NPTS * H1V];
__device__ float         g_tf2[(size_t)BB * MPTS * C2V];   // feat2 transposed [b][m][c]
__device__ __nv_bfloat16 g_W1h[H1V * CIN], g_W1l[H1V * CIN];
__device__ __nv_bfloat16 g_W2h[H2V * H1V], g_W2l[H2V * H1V];
__device__ int   g_idx[(size_t)BB * NPTS * 3];
__device__ float g_w  [(size_t)BB * NPTS * 3];

#define FLT_BIG 3.402823466e38f

// ---------------------------------------------------------------------------
// PTX helpers (sm_80-era features only — build targets plain sm_100)
// ---------------------------------------------------------------------------
__device__ __forceinline__ uint32_t smem_u32(const void* p) {
    uint32_t a;
    asm("{ .reg .u64 t; cvta.to.shared.u64 t, %1; cvt.u32.u64 %0, t; }" : "=r"(a) : "l"(p));
    return a;
}
__device__ __forceinline__ void cpa16(uint32_t dst, const void* src) {
    asm volatile("cp.async.cg.shared.global [%0], [%1], 16;" :: "r"(dst), "l"(src));
}
__device__ __forceinline__ void ldmx4(uint32_t* r, uint32_t addr) {
    asm volatile("ldmatrix.sync.aligned.m8n8.x4.shared.b16 {%0,%1,%2,%3}, [%4];"
                 : "=r"(r[0]), "=r"(r[1]), "=r"(r[2]), "=r"(r[3]) : "r"(addr));
}
__device__ __forceinline__ void mma16816(float* d, const uint32_t* a,
                                         uint32_t b0, uint32_t b1) {
    asm volatile(
        "mma.sync.aligned.m16n8k16.row.col.f32.bf16.bf16.f32 "
        "{%0,%1,%2,%3}, {%4,%5,%6,%7}, {%8,%9}, {%0,%1,%2,%3};"
        : "+f"(d[0]), "+f"(d[1]), "+f"(d[2]), "+f"(d[3])
        : "r"(a[0]), "r"(a[1]), "r"(a[2]), "r"(a[3]), "r"(b0), "r"(b1));
}
__device__ __forceinline__ void split2(float y, __nv_bfloat16& h, __nv_bfloat16& l) {
    h = __float2bfloat16_rn(y);
    l = __float2bfloat16_rn(y - __bfloat162float(h));
}

// ---------------------------------------------------------------------------
// Fused heterogeneous prep kernel (unchanged from R7 pass)
// ---------------------------------------------------------------------------
#define NN_BLKS   (BB * NPTS / 8)                         // 8192
#define F1_BLKS   ((NPTS / 32) * (C1V / 64) * BB)         // 8192
#define F2T_BLKS  ((MPTS / 32) * (C2V / 32) * BB)         // 4096
#define WS1_BLKS  (H1V * CIN / 256)                       // 512
#define WS2_BLKS  (H2V * H1V / 256)                       // 256
#define PREP_BLKS (NN_BLKS + F1_BLKS + F2T_BLKS + WS1_BLKS + WS2_BLKS)

__global__ __launch_bounds__(256) void prep_kernel(
    const float* __restrict__ xyz1, const float* __restrict__ xyz2,
    const float* __restrict__ feat1, const float* __restrict__ feat2,
    const float* __restrict__ w1, const float* __restrict__ w2)
{
    __shared__ __align__(16) char sbuf[16384];
    const int bid = blockIdx.x;
    const int tid = threadIdx.x;

    if (bid < NN_BLKS + F1_BLKS) {
        if ((bid & 1) == 0) {
            // ---------------- nn part ----------------
            float* sx = reinterpret_cast<float*>(sbuf);
            float* sy = sx + MPTS;
            float* sz = sy + MPTS;
            float* sn = sz + MPTS;
            const int warp = tid >> 5;
            const int lane = tid & 31;
            const int p0   = (bid >> 1) * 8;
            const int b    = p0 / NPTS;

            const float* x2 = xyz2 + (size_t)b * MPTS * 3;
            for (int i = tid; i < MPTS; i += 256) {
                float a = x2[i*3+0], c = x2[i*3+1], d = x2[i*3+2];
                sx[i] = a; sy[i] = c; sz[i] = d;
                sn[i] = a*a + c*c + d*d;
            }
            __syncthreads();

            const int n = (p0 + warp) % NPTS;
            const float* q = xyz1 + ((size_t)b * NPTS + n) * 3;
            const float qx = q[0], qy = q[1], qz = q[2];
            const float qn = qx*qx + qy*qy + qz*qz;

            float d0 = FLT_BIG, d1 = FLT_BIG, d2 = FLT_BIG;
            int   i0 = -1, i1 = -1, i2 = -1;

            #pragma unroll 4
            for (int j = 0; j < MPTS / 32; j++) {
                const int m = j * 32 + lane;
                const float dot = qx*sx[m] + qy*sy[m] + qz*sz[m];
                const float d = qn + sn[m] - 2.0f * dot;
                if (d < d2) {
                    if (d < d1) {
                        d2 = d1; i2 = i1;
                        if (d < d0) { d1 = d0; i1 = i0; d0 = d; i0 = m; }
                        else        { d1 = d;  i1 = m; }
                    } else { d2 = d; i2 = m; }
                }
            }

            float rd[3]; int ri[3];
            #pragma unroll
            for (int k = 0; k < 3; k++) {
                float v = d0;
                #pragma unroll
                for (int off = 16; off; off >>= 1)
                    v = fminf(v, __shfl_xor_sync(0xffffffffu, v, off));
                const unsigned mask = __ballot_sync(0xffffffffu, d0 == v);
                const int src = __ffs(mask) - 1;
                const int widx = __shfl_sync(0xffffffffu, i0, src);
                rd[k] = v; ri[k] = widx;
                if (lane == src) { d0 = d1; i0 = i1; d1 = d2; i1 = i2; d2 = FLT_BIG; i2 = -1; }
            }

            if (lane == 0) {
                const float w0 = 1.0f / (rd[0] + 1e-8f);
                const float w1v = 1.0f / (rd[1] + 1e-8f);
                const float w2v = 1.0f / (rd[2] + 1e-8f);
                const float s  = 1.0f / (w0 + w1v + w2v);
                const size_t base = ((size_t)b * NPTS + n) * 3;
                g_w[base+0] = w0 * s; g_w[base+1] = w1v * s; g_w[base+2] = w2v * s;
                g_idx[base+0] = ri[0]; g_idx[base+1] = ri[1]; g_idx[base+2] = ri[2];
            }
        } else {
            // ---------------- feat1 -> X part ----------------
            float (*s)[65] = reinterpret_cast<float(*)[65]>(sbuf);
            const int f  = bid >> 1;
            const int n0 = (f & 127) * 32;
            const int c0 = ((f >> 7) & 3) * 64;
            const int b  = f >> 9;
            for (int i = tid; i < 64 * 32; i += 256) {
                const int cl = i >> 5, nl = i & 31;
                s[nl][cl] = feat1[((size_t)b * C1V + c0 + cl) * NPTS + n0 + nl];
            }
            __syncthreads();
            const int n_l = tid >> 3, seg = tid & 7;
            const size_t orow = ((size_t)(b * NPTS + n0 + n_l)) * CIN + C2V + c0 + seg * 8;
            __nv_bfloat16 h[8], l[8];
            #pragma unroll
            for (int t = 0; t < 8; t++) split2(s[n_l][seg * 8 + t], h[t], l[t]);
            *reinterpret_cast<uint4*>(g_Xh + orow) = *reinterpret_cast<uint4*>(h);
            *reinterpret_cast<uint4*>(g_Xl + orow) = *reinterpret_cast<uint4*>(l);
        }
    } else if (bid < NN_BLKS + F1_BLKS + F2T_BLKS) {
        // ---------------- feat2 transpose part ----------------
        float (*s)[33] = reinterpret_cast<float(*)[33]>(sbuf);
        const int t  = bid - (NN_BLKS + F1_BLKS);
        const int m0 = (t & 31) * 32;
        const int c0 = ((t >> 5) & 7) * 32;
        const int b  = t >> 8;
        for (int i = tid; i < 1024; i += 256) {
            const int cl = i >> 5, ml = i & 31;
            s[ml][cl] = feat2[((size_t)b * C2V + c0 + cl) * MPTS + m0 + ml];
        }
        __syncthreads();
        for (int i = tid; i < 1024; i += 256) {
            const int ml = i >> 5, cl = i & 31;
            g_tf2[((size_t)(b * MPTS + m0 + ml)) * C2V + c0 + cl] = s[ml][cl];
        }
    } else {
        // ---------------- weight split part ----------------
        const int u = bid - (NN_BLKS + F1_BLKS + F2T_BLKS);
        if (u < WS1_BLKS) {
            const int i = u * 256 + tid;
            split2(w1[i], g_W1h[i], g_W1l[i]);
        } else {
            const int i = (u - WS1_BLKS) * 256 + tid;
            split2(w2[i], g_W2h[i], g_W2l[i]);
        }
    }
}

// ---------------------------------------------------------------------------
// interpolate -> X[b][n][0..255] (bf16 hi/lo). One warp per point.
// ---------------------------------------------------------------------------
__global__ __launch_bounds__(256) void interp_t()
{
    const int warp = threadIdx.x >> 5;
    const int lane = threadIdx.x & 31;
    const int gn = blockIdx.x * 8 + warp;
    const int b = gn >> 12;
    const size_t base3 = (size_t)gn * 3;
    const int   j0 = g_idx[base3+0], j1 = g_idx[base3+1], j2 = g_idx[base3+2];
    const float w0 = g_w[base3+0],   w1 = g_w[base3+1],   w2 = g_w[base3+2];
    const float* f0 = g_tf2 + ((size_t)(b * MPTS + j0)) * C2V;
    const float* f1 = g_tf2 + ((size_t)(b * MPTS + j1)) * C2V;
    const float* f2 = g_tf2 + ((size_t)(b * MPTS + j2)) * C2V;
    const size_t orow = (size_t)gn * CIN;

    #pragma unroll
    for (int half = 0; half < 2; half++) {
        const int c = half * 128 + lane * 4;
        const float4 a = *reinterpret_cast<const float4*>(f0 + c);
        const float4 d = *reinterpret_cast<const float4*>(f1 + c);
        const float4 e = *reinterpret_cast<const float4*>(f2 + c);
        float y[4] = { w0*a.x + w1*d.x + w2*e.x, w0*a.y + w1*d.y + w2*e.y,
                       w0*a.z + w1*d.z + w2*e.z, w0*a.w + w1*d.w + w2*e.w };
        __nv_bfloat16 h[4], l[4];
        #pragma unroll
        for (int t = 0; t < 4; t++) split2(y[t], h[t], l[t]);
        *reinterpret_cast<uint2*>(g_Xh + orow + c) = *reinterpret_cast<uint2*>(h);
        *reinterpret_cast<uint2*>(g_Xl + orow + c) = *reinterpret_cast<uint2*>(l);
    }
}

// ---------------------------------------------------------------------------
// bf16-split GEMM via mma.sync + BN + ReLU.  Round-8 change: k-chunk 32 with
// hi/lo interleaved per 128B row -> 32KB/buffer, 64KB/CTA total, and
// __launch_bounds__(256,2) => 2 CTAs/SM so mainloops cover barriers/epilogues.
// Buffer layout (32KB): W rows [0,16K): row r = [Wh(64B) | Wl(64B)], swizzled
// in 8x16B segs (s ^ (r&7)); X rows [16K,32K) same. Segment s: hi=scol, lo=scol+4.
// ---------------------------------------------------------------------------
#define SMEM_GEMM 65536

template<int KTOT, bool FP32OUT>
__global__ __launch_bounds__(256, 2)
void gemm_mma(const __nv_bfloat16* __restrict__ Wh, const __nv_bfloat16* __restrict__ Wl,
              const __nv_bfloat16* __restrict__ Bh, const __nv_bfloat16* __restrict__ Bl,
              const float* __restrict__ gamma, const float* __restrict__ beta,
              float* __restrict__ outF, __nv_bfloat16* __restrict__ outH,
              __nv_bfloat16* __restrict__ outL)
{
    extern __shared__ __align__(128) char smem[];
    const uint32_t sb = smem_u32(smem);
    const int tid  = threadIdx.x;
    const int wid  = tid >> 5;
    const int ln   = tid & 31;
    const int wrow = wid >> 2;
    const int wcol = wid & 3;
    const int n0   = blockIdx.x * 128;
    const int o0   = blockIdx.y * 128;
    const int b    = blockIdx.z;

    float acc[4][4][4];
    #pragma unroll
    for (int mi = 0; mi < 4; mi++)
        #pragma unroll
        for (int ni = 0; ni < 4; ni++)
            #pragma unroll
            for (int e = 0; e < 4; e++) acc[mi][ni][e] = 0.0f;

    constexpr int NC = KTOT / 32;

    const int rA  = wrow * 64 + (ln & 15);
    const int rB  = wcol * 32 + (ln & 15);
    const uint32_t sunit = (uint32_t)(ln >> 4);   // 0/1: k 0-7 vs 8-15 of the k16 step
    const uint32_t lswz  = (uint32_t)(ln & 7);

    // chunk loader: 2048 cpa16 per chunk (8 per thread)
    auto load_chunk = [&](int c) {
        const uint32_t ab = sb + (uint32_t)(c & 1) * 32768u;
        const int k0 = c * 32;
        #pragma unroll
        for (int it = 0; it < 8; it++) {
            const int i = tid + it * 256;
            const int region = i >> 10;           // 0 = W, 1 = X
            const int row = (i >> 3) & 127;
            const int s = i & 7;                  // 0-3 hi segs, 4-7 lo segs
            const uint32_t sw = (uint32_t)region * 16384u + (uint32_t)row * 128u
                              + (uint32_t)((s ^ (row & 7)) << 4);
            const int kofs = k0 + (s & 3) * 8;
            const void* src;
            if (region == 0)
                src = (s < 4 ? (const void*)(Wh + (size_t)(o0 + row) * KTOT + kofs)
                             : (const void*)(Wl + (size_t)(o0 + row) * KTOT + kofs));
            else
                src = (s < 4 ? (const void*)(Bh + ((size_t)b * NPTS + n0 + row) * KTOT + kofs)
                             : (const void*)(Bl + ((size_t)b * NPTS + n0 + row) * KTOT + kofs));
            cpa16(ab + sw, src);
        }
        asm volatile("cp.async.commit_group;");
    };

    load_chunk(0);

    for (int c = 0; c < NC; c++) {
        if (c + 1 < NC) {
            load_chunk(c + 1);
            asm volatile("cp.async.wait_group 1;" ::: "memory");
        } else {
            asm volatile("cp.async.wait_group 0;" ::: "memory");
        }
        __syncthreads();

        const uint32_t ab = sb + (uint32_t)(c & 1) * 32768u;
        #pragma unroll
        for (int ks = 0; ks < 2; ks++) {
            const uint32_t scol = (uint32_t)(ks * 2) + sunit;       // 0..3
            const uint32_t kswzH = ((scol ^ lswz) << 4);
            const uint32_t kswzL = (((scol + 4u) ^ lswz) << 4);

            uint32_t bh[2][4], bl[2][4];
            #pragma unroll
            for (int np = 0; np < 2; np++) {
                const uint32_t rbase = 16384u + (uint32_t)(rB + np * 16) * 128u;
                ldmx4(bh[np], ab + rbase + kswzH);
                ldmx4(bl[np], ab + rbase + kswzL);
            }
            #pragma unroll
            for (int mi = 0; mi < 4; mi++) {
                const uint32_t abase = (uint32_t)(rA + mi * 16) * 128u;
                uint32_t ah[4], al[4];
                ldmx4(ah, ab + abase + kswzH);
                ldmx4(al, ab + abase + kswzL);
                #pragma unroll
                for (int ni = 0; ni < 4; ni++) {
                    const int np = ni >> 1, hf = ni & 1;
                    const uint32_t b0h = bh[np][hf], b1h = bh[np][2 + hf];
                    const uint32_t b0l = bl[np][hf], b1l = bl[np][2 + hf];
                    mma16816(acc[mi][ni], ah, b0h, b1h);
                    mma16816(acc[mi][ni], ah, b0l, b1l);
                    mma16816(acc[mi][ni], al, b0h, b1h);
                }
            }
        }
        __syncthreads();
    }

    // ---------------- epilogue ----------------
    const float inv = rsqrtf(1.0f + 1e-5f);
    const int g = ln >> 2, t = ln & 3;

    if (FP32OUT) {
        #pragma unroll
        for (int mi = 0; mi < 4; mi++) {
            const int o_a = o0 + wrow * 64 + mi * 16 + g;
            const int o_b = o_a + 8;
            const float scA = gamma[o_a] * inv, biA = beta[o_a];
            const float scB = gamma[o_b] * inv, biB = beta[o_b];
            float* rowA = outF + ((size_t)(b * H2V + o_a)) * NPTS + n0;
            float* rowB = outF + ((size_t)(b * H2V + o_b)) * NPTS + n0;
            #pragma unroll
            for (int ni = 0; ni < 4; ni++) {
                const int n = wcol * 32 + ni * 8 + 2 * t;
                float2 va, vb;
                va.x = fmaxf(fmaf(acc[mi][ni][0], scA, biA), 0.0f);
                va.y = fmaxf(fmaf(acc[mi][ni][1], scA, biA), 0.0f);
                vb.x = fmaxf(fmaf(acc[mi][ni][2], scB, biB), 0.0f);
                vb.y = fmaxf(fmaf(acc[mi][ni][3], scB, biB), 0.0f);
                *reinterpret_cast<float2*>(rowA + n) = va;
                *reinterpret_cast<float2*>(rowB + n) = vb;
            }
        }
    } else {
        // two half-tiles of 64 o-rows each: S[64][129] fp32 = 33KB fits 64KB
        float* S = reinterpret_cast<float*>(smem);
        #pragma unroll
        for (int half = 0; half < 2; half++) {
            __syncthreads();
            if (wrow == half) {
                #pragma unroll
                for (int mi = 0; mi < 4; mi++) {
                    const int ol_a = mi * 16 + g;          // local o in [0,64)
                    const int ol_b = ol_a + 8;
                    const int oga = o0 + half * 64 + ol_a;
                    const int ogb = oga + 8;
                    const float scA = gamma[oga] * inv, biA = beta[oga];
                    const float scB = gamma[ogb] * inv, biB = beta[ogb];
                    #pragma unroll
                    for (int ni = 0; ni < 4; ni++) {
                        const int nl = wcol * 32 + ni * 8 + 2 * t;
                        S[ol_a * 129 + nl]     = fmaxf(fmaf(acc[mi][ni][0], scA, biA), 0.0f);
                        S[ol_a * 129 + nl + 1] = fmaxf(fmaf(acc[mi][ni][1], scA, biA), 0.0f);
                        S[ol_b * 129 + nl]     = fmaxf(fmaf(acc[mi][ni][2], scB, biB), 0.0f);
                        S[ol_b * 129 + nl + 1] = fmaxf(fmaf(acc[mi][ni][3], scB, biB), 0.0f);
                    }
                }
            }
            __syncthreads();
            const int n_l = tid >> 1, oh = (tid & 1) * 32;
            const size_t drow = ((size_t)(b * NPTS + n0 + n_l)) * H1V + o0 + half * 64 + oh;
            #pragma unroll
            for (int gs = 0; gs < 4; gs++) {
                __nv_bfloat16 h[8], l[8];
                #pragma unroll
                for (int t2 = 0; t2 < 8; t2++)
                    split2(S[(oh + gs * 8 + t2) * 129 + n_l], h[t2], l[t2]);
                *reinterpret_cast<uint4*>(outH + drow + gs * 8) = *reinterpret_cast<uint4*>(h);
                *reinterpret_cast<uint4*>(outL + drow + gs * 8) = *reinterpret_cast<uint4*>(l);
            }
        }
    }
}

// ---------------------------------------------------------------------------
extern "C" void kernel_launch(void* const* d_in, const int* in_sizes, int n_in,
                              void* d_out, int out_size)
{
    const float* xyz1   = (const float*)d_in[0];
    const float* xyz2   = (const float*)d_in[1];
    const float* feat1  = (const float*)d_in[2];
    const float* feat2  = (const float*)d_in[3];
    const float* w1     = (const float*)d_in[4];
    const float* gamma1 = (const float*)d_in[5];
    const float* beta1  = (const float*)d_in[6];
    const float* w2     = (const float*)d_in[7];
    const float* gamma2 = (const float*)d_in[8];
    const float* beta2  = (const float*)d_in[9];
    float* out = (float*)d_out;

    __nv_bfloat16 *Xh, *Xl, *X1h, *X1l, *W1h, *W1l, *W2h, *W2l;
    cudaGetSymbolAddress((void**)&Xh,  g_Xh);
    cudaGetSymbolAddress((void**)&Xl,  g_Xl);
    cudaGetSymbolAddress((void**)&X1h, g_X1h);
    cudaGetSymbolAddress((void**)&X1l, g_X1l);
    cudaGetSymbolAddress((void**)&W1h, g_W1h);
    cudaGetSymbolAddress((void**)&W1l, g_W1l);
    cudaGetSymbolAddress((void**)&W2h, g_W2h);
    cudaGetSymbolAddress((void**)&W2l, g_W2l);

    cudaFuncSetAttribute(gemm_mma<CIN, false>, cudaFuncAttributeMaxDynamicSharedMemorySize, SMEM_GEMM);
    cudaFuncSetAttribute(gemm_mma<H1V, true>,  cudaFuncAttributeMaxDynamicSharedMemorySize, SMEM_GEMM);

    // 1) fused heterogeneous prep
    prep_kernel<<<PREP_BLKS, 256>>>(xyz1, xyz2, feat1, feat2, w1, w2);

    // 2) interpolation
    interp_t<<<BB * NPTS / 8, 256>>>();

    // 3) layer 1: W1[256,512] x X[b, n, 512] -> X1 (bf16 hi/lo, [b][n][256])
    gemm_mma<CIN, false><<<dim3(NPTS / 128, H1V / 128, BB), 256, SMEM_GEMM>>>(
        W1h, W1l, Xh, Xl, gamma1, beta1, nullptr, X1h, X1l);
    // 4) layer 2: W2[256,256] x X1[b, n, 256] -> out fp32 [b][256][n]
    gemm_mma<H1V, true><<<dim3(NPTS / 128, H2V / 128, BB), 256, SMEM_GEMM>>>(
        W2h, W2l, X1h, X1l, gamma2, beta2, out, nullptr, nullptr);
}